// round 1
// baseline (speedup 1.0000x reference)
#include <cuda_runtime.h>
#include <math.h>

// Problem constants
#define Bn 2
#define Tn 32
#define Nn 64
#define FINn 64
#define FOUTn 64
#define EDIMn 16
#define BT (Bn*Tn)            // 64
#define ROWS (BT*Nn)          // 4096  rows of GEMM1 = (b,t,j)
#define KE (Nn*EDIMn)         // 1024  contraction dim of GEMM2 = (j,e)
#define EO (EDIMn*FOUTn)      // 1024  cols of GEMM1 = (e,o)

// -------- device scratch (module-load allocated; no runtime allocs) --------
__device__ float g_xn[ROWS*FINn];        // [bt][j][f]   1 MB
__device__ float g_S[BT*FINn];           // [bt][f]
__device__ float g_h[Bn*Nn*KE];          // [b][i][(j,e)]  512 KB
__device__ float g_Wp[FINn*EO];          // [f][(e,o)]     256 KB
__device__ float g_P[ROWS*EO];           // [bt][j][(e,o)] == [bt][(j,e)][o]  16 MB
__device__ float g_part[4][BT*Nn*FOUTn]; // K-split partials of agg  4 MB
__device__ float g_T2[BT*FOUTn];         // eb2 bias contribution [bt][o]

__device__ __forceinline__ float gelu_exact(float v) {
    return 0.5f * v * (1.0f + erff(v * 0.70710678118654752f));
}

// -------- K1: GraphNorm over node axis + closed-form node-sum S --------
__global__ void k_norm(const float* __restrict__ x, const float* __restrict__ gw,
                       const float* __restrict__ gb, const float* __restrict__ gms) {
    int bt = blockIdx.x;           // 64 blocks
    int f  = threadIdx.x;          // 64 threads, one per feature
    const float* xp = x + bt * (Nn * FINn) + f;
    float s = 0.f, ss = 0.f;
#pragma unroll
    for (int n = 0; n < Nn; n++) { float v = xp[n * FINn]; s += v; ss += v * v; }
    float mean = s * (1.0f / Nn);
    float var  = ss * (1.0f / Nn) - mean * mean;
    float rstd = rsqrtf(var + 1e-5f);
    float gm = gms[0];
    float w = gw[f], bb = gb[f];
    float sub = mean * gm;
    float* xnp = g_xn + bt * (Nn * FINn) + f;
#pragma unroll
    for (int n = 0; n < Nn; n++) xnp[n * FINn] = (xp[n * FINn] - sub) * rstd * w + bb;
    // S[bt][f] = sum_j xn = 64*((mean - mean*gms)*rstd*w + gb)
    g_S[bt * FINn + f] = (float)Nn * ((mean - sub) * rstd * w + bb);
}

// -------- K2: edge hidden  h[b,i,j,e] = gelu(adj*ew1[e]+eb1[e]) --------
__global__ void k_edge(const float* __restrict__ adj, const float* __restrict__ ew1,
                       const float* __restrict__ eb1) {
    int idx = blockIdx.x * 256 + threadIdx.x;     // 131072 total
    if (idx >= Bn * Nn * Nn * EDIMn) return;
    int e  = idx & (EDIMn - 1);
    int ij = idx >> 4;
    float a = adj[ij];
    g_h[idx] = gelu_exact(a * ew1[e] + eb1[e]);
}

// -------- K3: permute ew2[e][f*64+o] -> Wp[f][(e,o)] --------
__global__ void k_wp(const float* __restrict__ ew2) {
    int idx = blockIdx.x * 256 + threadIdx.x;     // 65536 total
    int o = idx & 63;
    int f = (idx >> 6) & 63;
    int e = idx >> 12;
    g_Wp[f * EO + e * FOUTn + o] = ew2[idx];
}

// -------- K4: T2[bt][o] = sum_f S[bt][f]*eb2[f*64+o] --------
__global__ void k_t2(const float* __restrict__ eb2) {
    int bt = blockIdx.x;      // 64
    int o  = threadIdx.x;     // 64
    const float* Sp = g_S + bt * FINn;
    float acc = 0.f;
#pragma unroll 16
    for (int f = 0; f < FINn; f++) acc += Sp[f] * eb2[f * FOUTn + o];
    g_T2[bt * FOUTn + o] = acc;
}

// -------- tile compute macro: 4x4 register tile, 64-deep K --------
#define TILE_FMA(SA, SB)                                                     \
    _Pragma("unroll 16")                                                     \
    for (int k = 0; k < 64; k++) {                                           \
        float a0 = SA[ty4 + 0][k], a1 = SA[ty4 + 1][k];                      \
        float a2 = SA[ty4 + 2][k], a3 = SA[ty4 + 3][k];                      \
        float4 bv = *(const float4*)(&SB[k][tx4]);                           \
        acc00 += a0 * bv.x; acc01 += a0 * bv.y; acc02 += a0 * bv.z; acc03 += a0 * bv.w; \
        acc10 += a1 * bv.x; acc11 += a1 * bv.y; acc12 += a1 * bv.z; acc13 += a1 * bv.w; \
        acc20 += a2 * bv.x; acc21 += a2 * bv.y; acc22 += a2 * bv.z; acc23 += a2 * bv.w; \
        acc30 += a3 * bv.x; acc31 += a3 * bv.y; acc32 += a3 * bv.z; acc33 += a3 * bv.w; \
    }

#define DECL_ACC float acc00=0,acc01=0,acc02=0,acc03=0, acc10=0,acc11=0,acc12=0,acc13=0, \
                       acc20=0,acc21=0,acc22=0,acc23=0, acc30=0,acc31=0,acc32=0,acc33=0;

// -------- K5: GEMM1  P(4096x1024) = xn(4096x64) @ Wp(64x1024) --------
__global__ void __launch_bounds__(256) k_gemm1() {
    __shared__ float As[64][65];
    __shared__ float Bs[64][64];
    int r0 = blockIdx.y * 64;
    int c0 = blockIdx.x * 64;
    int tid = threadIdx.x;

    // A tile: 64 full rows (contiguous 4096 floats)
    const float4* Ag = (const float4*)(g_xn + r0 * FINn);
#pragma unroll
    for (int l = 0; l < 4; l++) {
        int e4 = tid + l * 256;
        float4 v = Ag[e4];
        int r = e4 >> 4, f = (e4 & 15) * 4;
        As[r][f] = v.x; As[r][f + 1] = v.y; As[r][f + 2] = v.z; As[r][f + 3] = v.w;
    }
    // B tile: Wp rows f=0..63, cols c0..c0+63
#pragma unroll
    for (int l = 0; l < 4; l++) {
        int e4 = tid + l * 256;
        int f = e4 >> 4, c = (e4 & 15) * 4;
        *(float4*)(&Bs[f][c]) = *(const float4*)(g_Wp + f * EO + c0 + c);
    }
    __syncthreads();

    int ty4 = (tid >> 4) * 4, tx4 = (tid & 15) * 4;
    DECL_ACC
    TILE_FMA(As, Bs)

    float* Cp = g_P + r0 * EO + c0;
    *(float4*)(Cp + (ty4 + 0) * EO + tx4) = make_float4(acc00, acc01, acc02, acc03);
    *(float4*)(Cp + (ty4 + 1) * EO + tx4) = make_float4(acc10, acc11, acc12, acc13);
    *(float4*)(Cp + (ty4 + 2) * EO + tx4) = make_float4(acc20, acc21, acc22, acc23);
    *(float4*)(Cp + (ty4 + 3) * EO + tx4) = make_float4(acc30, acc31, acc32, acc33);
}

// -------- K6: GEMM2  agg_part[ks](64x64) = H_b(64 x 256slice) @ P_bt(256slice x 64) --------
__global__ void __launch_bounds__(256) k_gemm2() {
    __shared__ float Hs[64][65];
    __shared__ float Ps[64][64];
    int ks = blockIdx.x & 3;
    int bt = blockIdx.x >> 2;           // 0..63 = b*32+t
    int b  = bt >> 5;
    const float* Hbase = g_h + b * (Nn * KE);    // rows i, stride 1024
    const float* Pbase = g_P + bt * (Nn * EO);   // rows je, stride 64 (contiguous)
    int tid = threadIdx.x;
    int ty4 = (tid >> 4) * 4, tx4 = (tid & 15) * 4;
    DECL_ACC

    for (int kc = 0; kc < 4; kc++) {
        int k0 = ks * 256 + kc * 64;
        // Hs[i][k] from Hbase[i*1024 + k0 + k]
#pragma unroll
        for (int l = 0; l < 4; l++) {
            int e4 = tid + l * 256;
            int i = e4 >> 4, kk = (e4 & 15) * 4;
            float4 v = *(const float4*)(Hbase + i * KE + k0 + kk);
            Hs[i][kk] = v.x; Hs[i][kk + 1] = v.y; Hs[i][kk + 2] = v.z; Hs[i][kk + 3] = v.w;
        }
        // Ps[k][o]: contiguous 64x64 block starting at Pbase + k0*64
        const float4* Pg = (const float4*)(Pbase + k0 * 64);
#pragma unroll
        for (int l = 0; l < 4; l++) {
            int e4 = tid + l * 256;
            float4 v = Pg[e4];
            int k = e4 >> 4, o = (e4 & 15) * 4;
            *(float4*)(&Ps[k][o]) = v;
        }
        __syncthreads();
        TILE_FMA(Hs, Ps)
        __syncthreads();
    }

    float* Cp = g_part[ks] + bt * (Nn * FOUTn);
    *(float4*)(Cp + (ty4 + 0) * FOUTn + tx4) = make_float4(acc00, acc01, acc02, acc03);
    *(float4*)(Cp + (ty4 + 1) * FOUTn + tx4) = make_float4(acc10, acc11, acc12, acc13);
    *(float4*)(Cp + (ty4 + 2) * FOUTn + tx4) = make_float4(acc20, acc21, acc22, acc23);
    *(float4*)(Cp + (ty4 + 3) * FOUTn + tx4) = make_float4(acc30, acc31, acc32, acc33);
}

// -------- K7: epilogue  y = gelu(xn@nw + nb + T2 + sum_ks part[ks]) --------
__global__ void __launch_bounds__(256) k_epi(const float* __restrict__ nw,
                                             const float* __restrict__ nb,
                                             float* __restrict__ out) {
    __shared__ float Xs[64][65];
    __shared__ float Ns[64][64];
    int bt = blockIdx.x;
    int tid = threadIdx.x;

    const float4* Xg = (const float4*)(g_xn + bt * (Nn * FINn));
#pragma unroll
    for (int l = 0; l < 4; l++) {
        int e4 = tid + l * 256;
        float4 v = Xg[e4];
        int r = e4 >> 4, f = (e4 & 15) * 4;
        Xs[r][f] = v.x; Xs[r][f + 1] = v.y; Xs[r][f + 2] = v.z; Xs[r][f + 3] = v.w;
    }
    const float4* Ng = (const float4*)nw;
#pragma unroll
    for (int l = 0; l < 4; l++) {
        int e4 = tid + l * 256;
        float4 v = Ng[e4];
        int f = e4 >> 4, o = (e4 & 15) * 4;
        *(float4*)(&Ns[f][o]) = v;
    }
    __syncthreads();

    int ty4 = (tid >> 4) * 4, tx4 = (tid & 15) * 4;
    DECL_ACC
    TILE_FMA(Xs, Ns)

    float4 nbv  = *(const float4*)(nb + tx4);
    float4 t2v  = *(const float4*)(g_T2 + bt * FOUTn + tx4);
    float accs[4][4] = {{acc00,acc01,acc02,acc03},{acc10,acc11,acc12,acc13},
                        {acc20,acc21,acc22,acc23},{acc30,acc31,acc32,acc33}};
    float base[4] = { nbv.x + t2v.x, nbv.y + t2v.y, nbv.z + t2v.z, nbv.w + t2v.w };

    float* op = out + bt * (Nn * FOUTn);
#pragma unroll
    for (int ii = 0; ii < 4; ii++) {
        int i = ty4 + ii;
        int off = i * FOUTn + tx4;
        float4 p0 = *(const float4*)(g_part[0] + bt * (Nn*FOUTn) + off);
        float4 p1 = *(const float4*)(g_part[1] + bt * (Nn*FOUTn) + off);
        float4 p2 = *(const float4*)(g_part[2] + bt * (Nn*FOUTn) + off);
        float4 p3 = *(const float4*)(g_part[3] + bt * (Nn*FOUTn) + off);
        float v0 = accs[ii][0] + base[0] + p0.x + p1.x + p2.x + p3.x;
        float v1 = accs[ii][1] + base[1] + p0.y + p1.y + p2.y + p3.y;
        float v2 = accs[ii][2] + base[2] + p0.z + p1.z + p2.z + p3.z;
        float v3 = accs[ii][3] + base[3] + p0.w + p1.w + p2.w + p3.w;
        *(float4*)(op + off) = make_float4(gelu_exact(v0), gelu_exact(v1),
                                           gelu_exact(v2), gelu_exact(v3));
    }
}

extern "C" void kernel_launch(void* const* d_in, const int* in_sizes, int n_in,
                              void* d_out, int out_size) {
    const float* x   = (const float*)d_in[0];
    const float* adj = (const float*)d_in[1];
    const float* ew1 = (const float*)d_in[2];
    const float* eb1 = (const float*)d_in[3];
    const float* ew2 = (const float*)d_in[4];
    const float* eb2 = (const float*)d_in[5];
    const float* nw  = (const float*)d_in[6];
    const float* nb  = (const float*)d_in[7];
    const float* gw  = (const float*)d_in[8];
    const float* gb  = (const float*)d_in[9];
    const float* gms = (const float*)d_in[10];
    float* out = (float*)d_out;

    k_norm<<<BT, FINn>>>(x, gw, gb, gms);
    k_edge<<<(Bn*Nn*Nn*EDIMn + 255) / 256, 256>>>(adj, ew1, eb1);
    k_wp<<<(EDIMn*FINn*FOUTn + 255) / 256, 256>>>(ew2);
    k_t2<<<BT, FOUTn>>>(eb2);
    k_gemm1<<<dim3(EO/64, ROWS/64), 256>>>();
    k_gemm2<<<BT*4, 256>>>();
    k_epi<<<BT, 256>>>(nw, nb, out);
}

// round 2
// speedup vs baseline: 1.2081x; 1.2081x over previous
#include <cuda_runtime.h>
#include <math.h>

// Problem constants
#define Bn 2
#define Tn 32
#define Nn 64
#define FINn 64
#define FOUTn 64
#define EDIMn 16
#define BT (Bn*Tn)            // 64
#define ROWS (BT*Nn)          // 4096
#define KE (Nn*EDIMn)         // 1024  contraction dim of GEMM2 = (j,e)
#define EO (EDIMn*FOUTn)      // 1024  cols of GEMM1 = (e,o)
#define EDGE_TOTAL (Bn*Nn*Nn*EDIMn)   // 131072
#define EDGE_BLOCKS (EDGE_TOTAL/256)  // 512

// -------- device scratch --------
__device__ float g_xn[ROWS*FINn];        // [bt][j][f]       1 MB
__device__ float g_h[Bn*Nn*KE];          // [b][i][(j,e)]    512 KB
__device__ float g_P[ROWS*EO];           // [bt][(j,e)][o]   16 MB
__device__ float g_part[5][BT*Nn*FOUTn]; // partials of agg + node-lin  5 MB
__device__ float g_T2[BT*FOUTn];         // eb2-bias contribution [bt][o]

__device__ __forceinline__ float gelu_exact(float v) {
    return 0.5f * v * (1.0f + erff(v * 0.70710678118654752f));
}

// ============ K1: fused prologue ============
// blocks 0..63   : GraphNorm for bt=blk (256 thr) + T2[bt][o] = sum_f S[f]*eb2[f,o]
// blocks 64..575 : edge hidden h = gelu(adj*ew1+eb1)
__global__ void __launch_bounds__(256) k_pre(const float* __restrict__ x,
                                             const float* __restrict__ adj,
                                             const float* __restrict__ ew1,
                                             const float* __restrict__ eb1,
                                             const float* __restrict__ eb2,
                                             const float* __restrict__ gw,
                                             const float* __restrict__ gb,
                                             const float* __restrict__ gms) {
    int blk = blockIdx.x;
    int tid = threadIdx.x;

    if (blk >= BT) {
        // ---- edge part ----
        int idx = (blk - BT) * 256 + tid;            // < 131072
        int e = idx & (EDIMn - 1);
        float a = adj[idx >> 4];
        g_h[idx] = gelu_exact(a * ew1[e] + eb1[e]);
        return;
    }

    // ---- norm + T2 part ----
    int bt = blk;
    int f = tid & 63;
    int g = tid >> 6;                                // 0..3
    __shared__ float sA[4][64];
    __shared__ float sB[4][64];
    __shared__ float sMul[64], sSub[64], sAdd[64], sSf[64];

    const float* xp = x + bt * (Nn * FINn) + f;
    float s = 0.f, ss = 0.f;
#pragma unroll
    for (int n = g * 16; n < g * 16 + 16; n++) {
        float v = xp[n * FINn];
        s += v; ss += v * v;
    }
    sA[g][f] = s; sB[g][f] = ss;
    __syncthreads();

    if (g == 0) {
        float st  = sA[0][f] + sA[1][f] + sA[2][f] + sA[3][f];
        float sst = sB[0][f] + sB[1][f] + sB[2][f] + sB[3][f];
        float mean = st * (1.0f / Nn);
        float var  = sst * (1.0f / Nn) - mean * mean;
        float rstd = rsqrtf(var + 1e-5f);
        float w = gw[f], bb = gb[f];
        float sub = mean * gms[0];
        sMul[f] = rstd * w;
        sSub[f] = sub;
        sAdd[f] = bb;
        sSf[f]  = (float)Nn * ((mean - sub) * rstd * w + bb);   // S[bt][f]
    }
    __syncthreads();

    float mul = sMul[f], sub = sSub[f], add = sAdd[f];
    float* xnp = g_xn + bt * (Nn * FINn) + f;
#pragma unroll
    for (int n = g * 16; n < g * 16 + 16; n++)
        xnp[n * FINn] = (xp[n * FINn] - sub) * mul + add;

    // T2 partial: thread (o=f, group g) sums f' in [g*16, g*16+16)
    int o = f;
    float acc = 0.f;
#pragma unroll
    for (int ff = g * 16; ff < g * 16 + 16; ff++)
        acc += sSf[ff] * eb2[ff * FOUTn + o];
    __syncthreads();            // sSf fully consumed before reusing sA
    sA[g][o] = acc;
    __syncthreads();
    if (g == 0)
        g_T2[bt * FOUTn + o] = sA[0][o] + sA[1][o] + sA[2][o] + sA[3][o];
}

// -------- tile compute: 4x4 register tile, 64-deep K --------
#define TILE_FMA(SA, SB)                                                     \
    _Pragma("unroll 16")                                                     \
    for (int k = 0; k < 64; k++) {                                           \
        float a0 = SA[ty4 + 0][k], a1 = SA[ty4 + 1][k];                      \
        float a2 = SA[ty4 + 2][k], a3 = SA[ty4 + 3][k];                      \
        float4 bv = *(const float4*)(&SB[k][tx4]);                           \
        acc00 += a0 * bv.x; acc01 += a0 * bv.y; acc02 += a0 * bv.z; acc03 += a0 * bv.w; \
        acc10 += a1 * bv.x; acc11 += a1 * bv.y; acc12 += a1 * bv.z; acc13 += a1 * bv.w; \
        acc20 += a2 * bv.x; acc21 += a2 * bv.y; acc22 += a2 * bv.z; acc23 += a2 * bv.w; \
        acc30 += a3 * bv.x; acc31 += a3 * bv.y; acc32 += a3 * bv.z; acc33 += a3 * bv.w; \
    }

#define DECL_ACC float acc00=0,acc01=0,acc02=0,acc03=0, acc10=0,acc11=0,acc12=0,acc13=0, \
                       acc20=0,acc21=0,acc22=0,acc23=0, acc30=0,acc31=0,acc32=0,acc33=0;

// ============ K2: GEMM1  P(4096x1024) = xn(4096x64) @ Wp(64x1024) ============
// Wp tile for column block e is ew2 rows directly: Wp[f][e*64+o] = ew2[e*4096 + f*64 + o]
__global__ void __launch_bounds__(256) k_gemm1(const float* __restrict__ ew2) {
    __shared__ float As[64][65];
    __shared__ float Bs[64][64];
    int r0 = blockIdx.y * 64;
    int e  = blockIdx.x;                 // 0..15, c0 = e*64
    int tid = threadIdx.x;

    const float4* Ag = (const float4*)(g_xn + r0 * FINn);
    const float4* Bg = (const float4*)(ew2 + e * (FINn * FOUTn));
#pragma unroll
    for (int l = 0; l < 4; l++) {
        int e4 = tid + l * 256;
        float4 v = Ag[e4];
        int r = e4 >> 4, f = (e4 & 15) * 4;
        As[r][f] = v.x; As[r][f + 1] = v.y; As[r][f + 2] = v.z; As[r][f + 3] = v.w;
        // B: contiguous [f][o] block of ew2
        *(float4*)(&Bs[0][0] + e4 * 4) = Bg[e4];
    }
    __syncthreads();

    int ty4 = (tid >> 4) * 4, tx4 = (tid & 15) * 4;
    DECL_ACC
    TILE_FMA(As, Bs)

    float* Cp = g_P + r0 * EO + e * 64;
    *(float4*)(Cp + (ty4 + 0) * EO + tx4) = make_float4(acc00, acc01, acc02, acc03);
    *(float4*)(Cp + (ty4 + 1) * EO + tx4) = make_float4(acc10, acc11, acc12, acc13);
    *(float4*)(Cp + (ty4 + 2) * EO + tx4) = make_float4(acc20, acc21, acc22, acc23);
    *(float4*)(Cp + (ty4 + 3) * EO + tx4) = make_float4(acc30, acc31, acc32, acc33);
}

// ============ K3: GEMM2 ============
// blocks 0..255 : agg partial ks = blk&3, bt = blk>>2 : H_b(64 x 256) @ P_bt(256 x 64)
// blocks 256..319: node-lin partial: xn[bt] (64x64) @ nw (64x64)  -> g_part[4]
__global__ void __launch_bounds__(256) k_gemm2(const float* __restrict__ nw) {
    __shared__ float Hs[64][65];
    __shared__ float Ps[64][64];
    int tid = threadIdx.x;
    int ty4 = (tid >> 4) * 4, tx4 = (tid & 15) * 4;
    DECL_ACC

    if (blockIdx.x < BT * 4) {
        int ks = blockIdx.x & 3;
        int bt = blockIdx.x >> 2;
        int b  = bt >> 5;
        const float* Hbase = g_h + b * (Nn * KE);
        const float* Pbase = g_P + bt * (Nn * EO);

        for (int kc = 0; kc < 4; kc++) {
            int k0 = ks * 256 + kc * 64;
#pragma unroll
            for (int l = 0; l < 4; l++) {
                int e4 = tid + l * 256;
                int i = e4 >> 4, kk = (e4 & 15) * 4;
                float4 v = *(const float4*)(Hbase + i * KE + k0 + kk);
                Hs[i][kk] = v.x; Hs[i][kk + 1] = v.y; Hs[i][kk + 2] = v.z; Hs[i][kk + 3] = v.w;
            }
            const float4* Pg = (const float4*)(Pbase + k0 * 64);
#pragma unroll
            for (int l = 0; l < 4; l++) {
                int e4 = tid + l * 256;
                *(float4*)(&Ps[0][0] + e4 * 4) = Pg[e4];
            }
            __syncthreads();
            TILE_FMA(Hs, Ps)
            __syncthreads();
        }

        float* Cp = g_part[ks] + bt * (Nn * FOUTn);
        *(float4*)(Cp + (ty4 + 0) * FOUTn + tx4) = make_float4(acc00, acc01, acc02, acc03);
        *(float4*)(Cp + (ty4 + 1) * FOUTn + tx4) = make_float4(acc10, acc11, acc12, acc13);
        *(float4*)(Cp + (ty4 + 2) * FOUTn + tx4) = make_float4(acc20, acc21, acc22, acc23);
        *(float4*)(Cp + (ty4 + 3) * FOUTn + tx4) = make_float4(acc30, acc31, acc32, acc33);
    } else {
        int bt = blockIdx.x - BT * 4;
        const float4* Xg = (const float4*)(g_xn + bt * (Nn * FINn));
        const float4* Ng = (const float4*)nw;
#pragma unroll
        for (int l = 0; l < 4; l++) {
            int e4 = tid + l * 256;
            float4 v = Xg[e4];
            int r = e4 >> 4, f = (e4 & 15) * 4;
            Hs[r][f] = v.x; Hs[r][f + 1] = v.y; Hs[r][f + 2] = v.z; Hs[r][f + 3] = v.w;
            *(float4*)(&Ps[0][0] + e4 * 4) = Ng[e4];
        }
        __syncthreads();
        TILE_FMA(Hs, Ps)
        float* Cp = g_part[4] + bt * (Nn * FOUTn);
        *(float4*)(Cp + (ty4 + 0) * FOUTn + tx4) = make_float4(acc00, acc01, acc02, acc03);
        *(float4*)(Cp + (ty4 + 1) * FOUTn + tx4) = make_float4(acc10, acc11, acc12, acc13);
        *(float4*)(Cp + (ty4 + 2) * FOUTn + tx4) = make_float4(acc20, acc21, acc22, acc23);
        *(float4*)(Cp + (ty4 + 3) * FOUTn + tx4) = make_float4(acc30, acc31, acc32, acc33);
    }
}

// ============ K4: elementwise epilogue ============
// y = gelu(sum_{s=0..4} part[s] + nb[o] + T2[bt][o])
__global__ void __launch_bounds__(256) k_epi(const float* __restrict__ nb,
                                             float* __restrict__ out) {
    int idx = blockIdx.x * 256 + threadIdx.x;   // 65536 float4s
    int e0 = idx * 4;
    int bt = e0 >> 12;
    int o  = e0 & 63;

    float4 p0 = *(const float4*)(g_part[0] + e0);
    float4 p1 = *(const float4*)(g_part[1] + e0);
    float4 p2 = *(const float4*)(g_part[2] + e0);
    float4 p3 = *(const float4*)(g_part[3] + e0);
    float4 p4 = *(const float4*)(g_part[4] + e0);
    float4 nbv = *(const float4*)(nb + o);
    float4 t2v = *(const float4*)(g_T2 + bt * FOUTn + o);

    float v0 = p0.x + p1.x + p2.x + p3.x + p4.x + nbv.x + t2v.x;
    float v1 = p0.y + p1.y + p2.y + p3.y + p4.y + nbv.y + t2v.y;
    float v2 = p0.z + p1.z + p2.z + p3.z + p4.z + nbv.z + t2v.z;
    float v3 = p0.w + p1.w + p2.w + p3.w + p4.w + nbv.w + t2v.w;
    *(float4*)(out + e0) = make_float4(gelu_exact(v0), gelu_exact(v1),
                                       gelu_exact(v2), gelu_exact(v3));
}

extern "C" void kernel_launch(void* const* d_in, const int* in_sizes, int n_in,
                              void* d_out, int out_size) {
    const float* x   = (const float*)d_in[0];
    const float* adj = (const float*)d_in[1];
    const float* ew1 = (const float*)d_in[2];
    const float* eb1 = (const float*)d_in[3];
    const float* ew2 = (const float*)d_in[4];
    const float* eb2 = (const float*)d_in[5];
    const float* nw  = (const float*)d_in[6];
    const float* nb  = (const float*)d_in[7];
    const float* gw  = (const float*)d_in[8];
    const float* gb  = (const float*)d_in[9];
    const float* gms = (const float*)d_in[10];
    float* out = (float*)d_out;

    k_pre<<<BT + EDGE_BLOCKS, 256>>>(x, adj, ew1, eb1, eb2, gw, gb, gms);
    k_gemm1<<<dim3(EO/64, ROWS/64), 256>>>(ew2);
    k_gemm2<<<BT*4 + BT, 256>>>(nw);
    k_epi<<<(ROWS*FOUTn)/(256*4), 256>>>(nb, out);
}